// round 13
// baseline (speedup 1.0000x reference)
#include <cuda_runtime.h>
#include <cuda_fp16.h>
#include <math.h>
#include <stdint.h>

// Problem constants
#define L_DIM 1024
#define B_DIM 8
#define E_DIM 1024
#define H_DIM 16
#define HD    64
#define M_ROWS (L_DIM * B_DIM)      // 8192
#define QKV_N  (3 * E_DIM)          // 3072
#define ROW3E  (3 * E_DIM)

// Scratch (allocation-free rule: __device__ globals), all fp16
__device__ __half g_qkv[(size_t)M_ROWS * QKV_N];   // fp16, Q pre-scaled by 0.125*log2e
__device__ __half g_attn[(size_t)M_ROWS * E_DIM];  // fp16 attention output
__device__ __half g_xh[(size_t)M_ROWS * E_DIM];    // fp16 x
__device__ __half g_wqkvh[(size_t)QKV_N * E_DIM];  // fp16 Wqkv
__device__ __half g_wouth[(size_t)E_DIM * E_DIM];  // fp16 Wout

__device__ __forceinline__ void mma_f16(float* c, const uint32_t* a, const uint32_t* b) {
    asm volatile(
        "mma.sync.aligned.m16n8k16.row.col.f32.f16.f16.f32 "
        "{%0,%1,%2,%3}, {%4,%5,%6,%7}, {%8,%9}, {%0,%1,%2,%3};\n"
        : "+f"(c[0]), "+f"(c[1]), "+f"(c[2]), "+f"(c[3])
        : "r"(a[0]), "r"(a[1]), "r"(a[2]), "r"(a[3]),
          "r"(b[0]), "r"(b[1]));
}

__device__ __forceinline__ void cp16(uint32_t sdst, const void* gsrc) {
    asm volatile("cp.async.cg.shared.global [%0], [%1], 16;\n"
                 :: "r"(sdst), "l"(gsrc));
}
__device__ __forceinline__ void cp_commit() {
    asm volatile("cp.async.commit_group;\n" ::: "memory");
}
__device__ __forceinline__ void cp_wait0() {
    asm volatile("cp.async.wait_group 0;\n" ::: "memory");
}
__device__ __forceinline__ void cp_wait1() {
    asm volatile("cp.async.wait_group 1;\n" ::: "memory");
}

__device__ __forceinline__ void ldm_x4(uint32_t* r, uint32_t addr) {
    asm volatile("ldmatrix.sync.aligned.m8n8.x4.shared.b16 {%0,%1,%2,%3}, [%4];"
        : "=r"(r[0]), "=r"(r[1]), "=r"(r[2]), "=r"(r[3]) : "r"(addr));
}
__device__ __forceinline__ void ldm_x4t(uint32_t* r, uint32_t addr) {
    asm volatile("ldmatrix.sync.aligned.m8n8.x4.trans.shared.b16 {%0,%1,%2,%3}, [%4];"
        : "=r"(r[0]), "=r"(r[1]), "=r"(r[2]), "=r"(r[3]) : "r"(addr));
}

__device__ __forceinline__ uint32_t packh2(float a, float b) {
    __half2 h = __floats2half2_rn(a, b);
    return *(uint32_t*)&h;
}

// ---------------------------------------------------------------------------
// Fused prepass: convert x, Wqkv, Wout to fp16 in one launch
// ---------------------------------------------------------------------------
#define NX4  (M_ROWS * E_DIM / 4)          // 2097152
#define NW14 (QKV_N * E_DIM / 4)           // 786432
#define NW24 (E_DIM * E_DIM / 4)           // 262144

__global__ void cvt_all_kernel(const float4* __restrict__ x,   __half2* __restrict__ xh,
                               const float4* __restrict__ wq,  __half2* __restrict__ wqh,
                               const float4* __restrict__ wo,  __half2* __restrict__ woh)
{
    int i = blockIdx.x * blockDim.x + threadIdx.x;
    const float4* src; __half2* dst; int j;
    if (i < NX4)                    { src = x;  dst = xh;  j = i; }
    else if (i < NX4 + NW14)        { src = wq; dst = wqh; j = i - NX4; }
    else if (i < NX4 + NW14 + NW24) { src = wo; dst = woh; j = i - NX4 - NW14; }
    else return;
    float4 v = src[j];
    dst[2 * j]     = __floats2half2_rn(v.x, v.y);
    dst[2 * j + 1] = __floats2half2_rn(v.z, v.w);
}

// ---------------------------------------------------------------------------
// FP16 GEMM: C[M,N] = A[M,K] @ W[N,K]^T + bias[N]  (fp32 accumulate)
// 512 threads = 16 warps (4x4 grid of 32x32 warp tiles), block tile 128x128,
// K-tile 64 halves, 3-stage cp.async pipeline, ldmatrix m16n8k16 fragments,
// smem row stride 72 halves. __launch_bounds__(512,2) -> 32 warps/SM so
// sync/LDSM bubbles interleave across warps (fills the idle tensor pipe).
// MODE 0: fp32 out.  MODE 1: fp16 qkv out (Q cols scaled by 0.125*log2e).
// ---------------------------------------------------------------------------
#define GSH 72                       // smem row stride in halves
#define GROWB 144                    // row bytes
#define STAGE_BYTES (2 * 128 * GROWB)  // 36864
#define QSCALE (0.125f * 1.44269504088896340736f)

template<int MODE>
__global__ void __launch_bounds__(512, 2) gemm_f16_kernel(
    const __half* __restrict__ A, const __half* __restrict__ W,
    const float* __restrict__ bias, void* __restrict__ Cv,
    int M, int N, int K)
{
    extern __shared__ char smg[];
    const uint32_t sbase = (uint32_t)__cvta_generic_to_shared(smg);

    const int tid  = threadIdx.x;
    const int lane = tid & 31;
    const int wid  = tid >> 5;
    const int wm   = (wid >> 2) * 32;     // 4 row-groups of 32
    const int wn   = (wid & 3) * 32;      // 4 col-groups of 32
    const int rowBase = blockIdx.y * 128;
    const int colBase = blockIdx.x * 128;

    // cp.async loader: 1024 chunks per operand, 2 per thread per operand
    const int r0 = tid >> 3;              // 0..63, rows r0 + p*64
    const int c8 = (tid & 7) * 8;
    const __half* Aptr = A + (size_t)(rowBase + r0) * K + c8;
    const __half* Wptr = W + (size_t)(colBase + r0) * K + c8;

    // ldmatrix lane address components (halves)
    const int arow = (lane & 15);
    const int acol = (lane >> 4) * 8;
    const int brow = ((lane >> 4) << 3) + (lane & 7);
    const int bcol = ((lane >> 3) & 1) * 8;

    float c[2][4][4];
#pragma unroll
    for (int mi = 0; mi < 2; mi++)
#pragma unroll
        for (int nj = 0; nj < 4; nj++)
#pragma unroll
            for (int r = 0; r < 4; r++) c[mi][nj][r] = 0.f;

#define GEMM_STAGE(buf, k0)                                                    \
    {                                                                          \
        uint32_t sb_ = sbase + (uint32_t)((buf) * STAGE_BYTES);                \
        _Pragma("unroll")                                                      \
        for (int p = 0; p < 2; p++) {                                          \
            uint32_t so_ = (uint32_t)((r0 + p * 64) * GROWB + (tid & 7) * 16); \
            cp16(sb_ + so_,                       Aptr + (size_t)(p * 64) * K + (k0)); \
            cp16(sb_ + (uint32_t)(128 * GROWB) + so_, Wptr + (size_t)(p * 64) * K + (k0)); \
        }                                                                      \
        cp_commit();                                                           \
    }

    const int T = K >> 6;   // 16 for K=1024
    GEMM_STAGE(0, 0);
    GEMM_STAGE(1, 64);

    int cbuf = 0;
    for (int t = 0; t < T; t++) {
        if (t == T - 1) cp_wait0(); else cp_wait1();
        __syncthreads();

        if (t + 2 < T) {
            int nb = cbuf + 2; if (nb >= 3) nb -= 3;
            GEMM_STAGE(nb, (t + 2) << 6);
        }

        const uint32_t Ab = sbase + (uint32_t)(cbuf * STAGE_BYTES);
        const uint32_t Wb = Ab + (uint32_t)(128 * GROWB);
#pragma unroll
        for (int ks = 0; ks < 4; ks++) {
            const int kk = ks * 16;
            uint32_t a[2][4], b[4][2];
#pragma unroll
            for (int mi = 0; mi < 2; mi++)
                ldm_x4(a[mi], Ab + (uint32_t)((wm + mi * 16 + arow) * GROWB + (kk + acol) * 2));
#pragma unroll
            for (int njp = 0; njp < 2; njp++)
                ldm_x4(&b[njp * 2][0],
                       Wb + (uint32_t)((wn + njp * 16 + brow) * GROWB + (kk + bcol) * 2));
#pragma unroll
            for (int mi = 0; mi < 2; mi++)
#pragma unroll
                for (int nj = 0; nj < 4; nj++)
                    mma_f16(c[mi][nj], a[mi], b[nj]);
        }
        cbuf++; if (cbuf == 3) cbuf = 0;
    }

    // epilogue
    const int g  = lane >> 2;
    const int tg = lane & 3;
    float scale = 1.f;
    if (MODE == 1) scale = (colBase < E_DIM) ? QSCALE : 1.f;
#pragma unroll
    for (int mi = 0; mi < 2; mi++) {
#pragma unroll
        for (int nj = 0; nj < 4; nj++) {
            int row0 = rowBase + wm + mi * 16 + g;
            int col  = colBase + wn + nj * 8 + tg * 2;
            float b0 = bias[col], b1 = bias[col + 1];
            if (MODE == 1) {
                __half* Ch = (__half*)Cv;
                __half2 v0 = __floats2half2_rn((c[mi][nj][0] + b0) * scale,
                                               (c[mi][nj][1] + b1) * scale);
                __half2 v1 = __floats2half2_rn((c[mi][nj][2] + b0) * scale,
                                               (c[mi][nj][3] + b1) * scale);
                *(__half2*)(Ch + (size_t)row0 * N + col)       = v0;
                *(__half2*)(Ch + (size_t)(row0 + 8) * N + col) = v1;
            } else {
                float* Cf = (float*)Cv;
                float2 v0 = make_float2(c[mi][nj][0] + b0, c[mi][nj][1] + b1);
                float2 v1 = make_float2(c[mi][nj][2] + b0, c[mi][nj][3] + b1);
                *(float2*)(Cf + (size_t)row0 * N + col)       = v0;
                *(float2*)(Cf + (size_t)(row0 + 8) * N + col) = v1;
            }
        }
    }
#undef GEMM_STAGE
}

// ---------------------------------------------------------------------------
// FP16 flash attention (fp32 softmax/accumulators), double-buffered K/V.
// One block = (b,h) x 128 q-rows, 256 thr (8 warps), warp owns 16 S rows.
// P stays in registers (S D-fragment packs directly into PV A-fragment).
// V via ldmatrix.x4.trans. Softmax in exp2 domain. 2 CTAs/SM.
// ---------------------------------------------------------------------------
__global__ void __launch_bounds__(256, 2) flash_f16_kernel(
    const __half* __restrict__ qkv, __half* __restrict__ outp)
{
    extern __shared__ __half smh[];
    __half* Kb0 = smh;                      // 64*GSH
    __half* Kb1 = Kb0 + 64 * GSH;
    __half* Vb0 = Kb1 + 64 * GSH;
    __half* Vb1 = Vb0 + 64 * GSH;
    __half* Qs  = Vb1 + 64 * GSH;           // 128*GSH (Q staging only)
    const uint32_t sK0 = (uint32_t)__cvta_generic_to_shared(Kb0);
    const uint32_t sV0 = (uint32_t)__cvta_generic_to_shared(Vb0);
    const uint32_t sQ  = (uint32_t)__cvta_generic_to_shared(Qs);
    const uint32_t BUF = (uint32_t)(64 * GROWB);   // 9216 B per K or V buffer

    const int tid  = threadIdx.x;
    const int wid  = tid >> 5;
    const int lane = tid & 31;
    const int g    = lane >> 2;
    const int tg   = lane & 3;
    const int wrow = wid * 16;

    const int bh = blockIdx.y;
    const int b  = bh >> 4;
    const int h  = bh & 15;
    const int q0 = blockIdx.x * 128;

    const size_t rstride = (size_t)B_DIM * ROW3E;   // 24576 halves

    // ldmatrix lane address components
    const int arow = (lane & 15);
    const int acol = (lane >> 4) * 8;
    const int brow = ((lane >> 4) << 3) + (lane & 7);
    const int bcol = ((lane >> 3) & 1) * 8;
    const int vrow = (lane & 15);
    const int vcol = (lane >> 4) * 8;

    // K/V loader: 64 rows x 8 chunks = 512 chunks, 2 per thread
    const int r0 = tid >> 3;               // 0..31, +p*32
    const int c8 = (tid & 7) * 8;          // halves
    const __half* kbase0 = qkv + (size_t)b * ROW3E + E_DIM + h * HD;

#define KV_STAGE(kt, buf)                                                      \
    {                                                                          \
        uint32_t sKb_ = sK0 + (buf) * BUF;                                     \
        uint32_t sVb_ = sV0 + (buf) * BUF;                                     \
        _Pragma("unroll")                                                      \
        for (int p = 0; p < 2; p++) {                                          \
            int rr_ = r0 + p * 32;                                             \
            uint32_t so_ = (uint32_t)(rr_ * GROWB + (tid & 7) * 16);           \
            const __half* kb_ = kbase0 + (size_t)((kt) * 64 + rr_) * rstride + c8; \
            cp16(sKb_ + so_, kb_);                                             \
            cp16(sVb_ + so_, kb_ + E_DIM);                                     \
        }                                                                      \
        cp_commit();                                                           \
    }

    // ---- stage Q (pre-scaled fp16), and KV tile 0 ----
    {
        const __half* qbase = qkv + (size_t)(q0 * B_DIM + b) * ROW3E + h * HD;
#pragma unroll
        for (int p = 0; p < 4; p++) {
            int f4 = tid + p * 256;
            int r  = f4 >> 3;              // 0..127
            int cc = (f4 & 7) * 8;
            cp16(sQ + (uint32_t)(r * GROWB + (f4 & 7) * 16),
                 qbase + (size_t)r * rstride + cc);
        }
    }
    KV_STAGE(0, 0);
    cp_wait0();
    __syncthreads();

    // ---- Q fragments into registers (warp-private rows) ----
    uint32_t qa[4][4];
#pragma unroll
    for (int ks = 0; ks < 4; ks++)
        ldm_x4(qa[ks], sQ + (uint32_t)((wrow + arow) * GROWB + (ks * 16 + acol) * 2));
    __syncwarp();

    float o[8][4];
#pragma unroll
    for (int nj = 0; nj < 8; nj++)
#pragma unroll
        for (int r = 0; r < 4; r++) o[nj][r] = 0.f;
    float m0 = -1e30f, m1 = -1e30f, l0 = 0.f, l1 = 0.f;

    for (int kt = 0; kt < 16; kt++) {
        const int cur = kt & 1;
        if (kt + 1 < 16) KV_STAGE(kt + 1, 1 - cur);

        const uint32_t sKc = sK0 + cur * BUF;
        const uint32_t sVc = sV0 + cur * BUF;

        // ---- S = Q K^T (log2-units) ----
        float s[8][4];
#pragma unroll
        for (int nj = 0; nj < 8; nj++)
#pragma unroll
            for (int r = 0; r < 4; r++) s[nj][r] = 0.f;

#pragma unroll
        for (int ks = 0; ks < 4; ks++) {
            const int kk = ks * 16;
            uint32_t kb[8][2];
#pragma unroll
            for (int njp = 0; njp < 4; njp++)
                ldm_x4(&kb[njp * 2][0],
                       sKc + (uint32_t)((njp * 16 + brow) * GROWB + (kk + bcol) * 2));
#pragma unroll
            for (int nj = 0; nj < 8; nj++)
                mma_f16(s[nj], qa[ks], kb[nj]);
        }

        // ---- online softmax, exp2 domain ----
        float rmax0 = -1e30f, rmax1 = -1e30f;
#pragma unroll
        for (int nj = 0; nj < 8; nj++) {
            rmax0 = fmaxf(rmax0, fmaxf(s[nj][0], s[nj][1]));
            rmax1 = fmaxf(rmax1, fmaxf(s[nj][2], s[nj][3]));
        }
        rmax0 = fmaxf(rmax0, __shfl_xor_sync(0xffffffffu, rmax0, 1));
        rmax0 = fmaxf(rmax0, __shfl_xor_sync(0xffffffffu, rmax0, 2));
        rmax1 = fmaxf(rmax1, __shfl_xor_sync(0xffffffffu, rmax1, 1));
        rmax1 = fmaxf(rmax1, __shfl_xor_sync(0xffffffffu, rmax1, 2));

        float nm0 = fmaxf(m0, rmax0), nm1 = fmaxf(m1, rmax1);
        float al0 = exp2f(m0 - nm0), al1 = exp2f(m1 - nm1);
        float rs0 = 0.f, rs1 = 0.f;
#pragma unroll
        for (int nj = 0; nj < 8; nj++) {
            s[nj][0] = exp2f(s[nj][0] - nm0);
            s[nj][1] = exp2f(s[nj][1] - nm0);
            s[nj][2] = exp2f(s[nj][2] - nm1);
            s[nj][3] = exp2f(s[nj][3] - nm1);
            rs0 += s[nj][0] + s[nj][1];
            rs1 += s[nj][2] + s[nj][3];
        }
        rs0 += __shfl_xor_sync(0xffffffffu, rs0, 1);
        rs0 += __shfl_xor_sync(0xffffffffu, rs0, 2);
        rs1 += __shfl_xor_sync(0xffffffffu, rs1, 1);
        rs1 += __shfl_xor_sync(0xffffffffu, rs1, 2);
        l0 = l0 * al0 + rs0;  m0 = nm0;
        l1 = l1 * al1 + rs1;  m1 = nm1;

#pragma unroll
        for (int nj = 0; nj < 8; nj++) {
            o[nj][0] *= al0; o[nj][1] *= al0;
            o[nj][2] *= al1; o[nj][3] *= al1;
        }

        // ---- O += P @ V : P packed from S fragments IN REGISTERS ----
#pragma unroll
        for (int ks = 0; ks < 4; ks++) {
            const int kk = ks * 16;
            uint32_t pa[4];
            pa[0] = packh2(s[2 * ks    ][0], s[2 * ks    ][1]);
            pa[1] = packh2(s[2 * ks    ][2], s[2 * ks    ][3]);
            pa[2] = packh2(s[2 * ks + 1][0], s[2 * ks + 1][1]);
            pa[3] = packh2(s[2 * ks + 1][2], s[2 * ks + 1][3]);
            uint32_t vb[8][2];
#pragma unroll
            for (int njp = 0; njp < 4; njp++)
                ldm_x4t(&vb[njp * 2][0],
                        sVc + (uint32_t)((kk + vrow) * GROWB + (njp * 16 + vcol) * 2));
#pragma unroll
            for (int nj = 0; nj < 8; nj++)
                mma_f16(o[nj], pa, vb[nj]);
        }

        cp_wait0();
        __syncthreads();
    }

    // ---- epilogue: normalize, fp16 out to [L,B,E] ----
    float inv0 = 1.0f / l0, inv1 = 1.0f / l1;
#pragma unroll
    for (int nj = 0; nj < 8; nj++) {
        int col = h * HD + nj * 8 + tg * 2;
        int rr = q0 + wrow + g;
        __half2 v0 = __floats2half2_rn(o[nj][0] * inv0, o[nj][1] * inv0);
        __half2 v1 = __floats2half2_rn(o[nj][2] * inv1, o[nj][3] * inv1);
        *(__half2*)(outp + (size_t)(rr * B_DIM + b) * E_DIM + col)       = v0;
        *(__half2*)(outp + (size_t)((rr + 8) * B_DIM + b) * E_DIM + col) = v1;
    }
#undef KV_STAGE
}

// ---------------------------------------------------------------------------
// Launch
// ---------------------------------------------------------------------------
extern "C" void kernel_launch(void* const* d_in, const int* in_sizes, int n_in,
                              void* d_out, int out_size)
{
    const float* x    = (const float*)d_in[0];
    const float* wqkv = (const float*)d_in[1];
    const float* bqkv = (const float*)d_in[2];
    const float* wout = (const float*)d_in[3];
    const float* bout = (const float*)d_in[4];
    float* out = (float*)d_out;

    __half *qkv, *attn, *xh, *wqkvh, *wouth;
    cudaGetSymbolAddress((void**)&qkv,   g_qkv);
    cudaGetSymbolAddress((void**)&attn,  g_attn);
    cudaGetSymbolAddress((void**)&xh,    g_xh);
    cudaGetSymbolAddress((void**)&wqkvh, g_wqkvh);
    cudaGetSymbolAddress((void**)&wouth, g_wouth);

    const size_t GEMM_SMEM  = (size_t)3 * STAGE_BYTES;                 // 110592
    const size_t FLASH_SMEM = (size_t)(4 * 64 + 128) * GROWB;          // 55296
    cudaFuncSetAttribute(gemm_f16_kernel<1>,
                         cudaFuncAttributeMaxDynamicSharedMemorySize, (int)GEMM_SMEM);
    cudaFuncSetAttribute(gemm_f16_kernel<0>,
                         cudaFuncAttributeMaxDynamicSharedMemorySize, (int)GEMM_SMEM);
    cudaFuncSetAttribute(flash_f16_kernel,
                         cudaFuncAttributeMaxDynamicSharedMemorySize, (int)FLASH_SMEM);

    // 0) fused prepass: convert inputs to fp16
    {
        int total = NX4 + NW14 + NW24;
        cvt_all_kernel<<<(total + 255) / 256, 256>>>(
            (const float4*)x, (__half2*)xh,
            (const float4*)wqkv, (__half2*)wqkvh,
            (const float4*)wout, (__half2*)wouth);
    }

    // 1) QKV projection (fp16 out, Q pre-scaled by 0.125*log2e)
    {
        dim3 grid(QKV_N / 128, M_ROWS / 128);
        gemm_f16_kernel<1><<<grid, 512, GEMM_SMEM>>>(xh, wqkvh, bqkv, qkv,
                                                     M_ROWS, QKV_N, E_DIM);
    }
    // 2) Attention (exp2-domain softmax, register-resident P)
    {
        dim3 grid(L_DIM / 128, B_DIM * H_DIM);
        flash_f16_kernel<<<grid, 256, FLASH_SMEM>>>(qkv, attn);
    }
    // 3) Output projection (fp32 out)
    {
        dim3 grid(E_DIM / 128, M_ROWS / 128);
        gemm_f16_kernel<0><<<grid, 512, GEMM_SMEM>>>(attn, wouth, bout, out,
                                                     M_ROWS, E_DIM, E_DIM);
    }
}

// round 14
// speedup vs baseline: 1.0581x; 1.0581x over previous
#include <cuda_runtime.h>
#include <cuda_fp16.h>
#include <math.h>
#include <stdint.h>

// Problem constants
#define L_DIM 1024
#define B_DIM 8
#define E_DIM 1024
#define H_DIM 16
#define HD    64
#define M_ROWS (L_DIM * B_DIM)      // 8192
#define QKV_N  (3 * E_DIM)          // 3072
#define ROW3E  (3 * E_DIM)

// Scratch (allocation-free rule: __device__ globals), all fp16
__device__ __half g_qkv[(size_t)M_ROWS * QKV_N];   // fp16, Q pre-scaled by 0.125*log2e
__device__ __half g_attn[(size_t)M_ROWS * E_DIM];  // fp16 attention output
__device__ __half g_xh[(size_t)M_ROWS * E_DIM];    // fp16 x
__device__ __half g_wqkvh[(size_t)QKV_N * E_DIM];  // fp16 Wqkv
__device__ __half g_wouth[(size_t)E_DIM * E_DIM];  // fp16 Wout
// flags[0..23]=qkv col counts, [24..31]=attn q-block counts, [32]=work counter
__device__ unsigned g_flags[40];

// Work-queue sizes
#define NQKV  1536
#define NFLS  1024
#define NPROJ 512
#define NTOT  (NQKV + NFLS + NPROJ)   // 3072

__device__ __forceinline__ void mma_f16(float* c, const uint32_t* a, const uint32_t* b) {
    asm volatile(
        "mma.sync.aligned.m16n8k16.row.col.f32.f16.f16.f32 "
        "{%0,%1,%2,%3}, {%4,%5,%6,%7}, {%8,%9}, {%0,%1,%2,%3};\n"
        : "+f"(c[0]), "+f"(c[1]), "+f"(c[2]), "+f"(c[3])
        : "r"(a[0]), "r"(a[1]), "r"(a[2]), "r"(a[3]),
          "r"(b[0]), "r"(b[1]));
}

__device__ __forceinline__ void cp16(uint32_t sdst, const void* gsrc) {
    asm volatile("cp.async.cg.shared.global [%0], [%1], 16;\n"
                 :: "r"(sdst), "l"(gsrc));
}
__device__ __forceinline__ void cp_commit() {
    asm volatile("cp.async.commit_group;\n" ::: "memory");
}
__device__ __forceinline__ void cp_wait0() {
    asm volatile("cp.async.wait_group 0;\n" ::: "memory");
}
__device__ __forceinline__ void cp_wait1() {
    asm volatile("cp.async.wait_group 1;\n" ::: "memory");
}

__device__ __forceinline__ void ldm_x4(uint32_t* r, uint32_t addr) {
    asm volatile("ldmatrix.sync.aligned.m8n8.x4.shared.b16 {%0,%1,%2,%3}, [%4];"
        : "=r"(r[0]), "=r"(r[1]), "=r"(r[2]), "=r"(r[3]) : "r"(addr));
}
__device__ __forceinline__ void ldm_x4t(uint32_t* r, uint32_t addr) {
    asm volatile("ldmatrix.sync.aligned.m8n8.x4.trans.shared.b16 {%0,%1,%2,%3}, [%4];"
        : "=r"(r[0]), "=r"(r[1]), "=r"(r[2]), "=r"(r[3]) : "r"(addr));
}

__device__ __forceinline__ uint32_t packh2(float a, float b) {
    __half2 h = __floats2half2_rn(a, b);
    return *(uint32_t*)&h;
}

__device__ __forceinline__ unsigned ld_acq(const unsigned* p) {
    unsigned v;
    asm volatile("ld.global.acquire.gpu.b32 %0, [%1];" : "=r"(v) : "l"(p));
    return v;
}

// ---------------------------------------------------------------------------
// Fused prepass: convert x, Wqkv, Wout to fp16; block 0 resets flags
// ---------------------------------------------------------------------------
#define NX4  (M_ROWS * E_DIM / 4)          // 2097152
#define NW14 (QKV_N * E_DIM / 4)           // 786432
#define NW24 (E_DIM * E_DIM / 4)           // 262144

__global__ void cvt_all_kernel(const float4* __restrict__ x,   __half2* __restrict__ xh,
                               const float4* __restrict__ wq,  __half2* __restrict__ wqh,
                               const float4* __restrict__ wo,  __half2* __restrict__ woh)
{
    if (blockIdx.x == 0 && threadIdx.x < 40) g_flags[threadIdx.x] = 0u;
    int i = blockIdx.x * blockDim.x + threadIdx.x;
    const float4* src; __half2* dst; int j;
    if (i < NX4)                    { src = x;  dst = xh;  j = i; }
    else if (i < NX4 + NW14)        { src = wq; dst = wqh; j = i - NX4; }
    else if (i < NX4 + NW14 + NW24) { src = wo; dst = woh; j = i - NX4 - NW14; }
    else return;
    float4 v = src[j];
    dst[2 * j]     = __floats2half2_rn(v.x, v.y);
    dst[2 * j + 1] = __floats2half2_rn(v.z, v.w);
}

// ---------------------------------------------------------------------------
// Fused persistent kernel: QKV gemm tiles -> flash tiles -> out-proj tiles,
// pulled from one global counter; cross-stage deps via acquire/release flags.
// All tile math bit-identical to the R12 champion kernels.
// ---------------------------------------------------------------------------
#define GSH 72                         // smem row stride in halves
#define GROWB 144                      // row bytes
#define STAGE_BYTES (2 * 128 * GROWB)  // 36864
#define QSCALE (0.125f * 1.44269504088896340736f)
#define FUSED_SMEM ((size_t)3 * STAGE_BYTES)   // 110592 (superset of flash's 55296)

__global__ void __launch_bounds__(256, 2) fused_kernel(
    const __half* __restrict__ xh,    const __half* __restrict__ wqkvh,
    const float*  __restrict__ bqkv,  const __half* __restrict__ wouth,
    const float*  __restrict__ bout,  __half* __restrict__ qkv,
    __half* __restrict__ attn,        float* __restrict__ out)
{
    extern __shared__ char smg[];
    __shared__ unsigned w_s;
    const uint32_t sbase = (uint32_t)__cvta_generic_to_shared(smg);

    const int tid  = threadIdx.x;
    const int lane = tid & 31;
    const int wid  = tid >> 5;
    const int g    = lane >> 2;
    const int tg   = lane & 3;

    // ldmatrix lane address components (shared by both tile types)
    const int arow = (lane & 15);
    const int acol = (lane >> 4) * 8;
    const int brow = ((lane >> 4) << 3) + (lane & 7);
    const int bcol = ((lane >> 3) & 1) * 8;
    const int vrow = (lane & 15);
    const int vcol = (lane >> 4) * 8;

    for (;;) {
        if (tid == 0) w_s = atomicAdd(&g_flags[32], 1u);
        __syncthreads();
        const unsigned w = w_s;
        if (w >= NTOT) return;

        if (w < NQKV + NPROJ ? (w < NQKV || w >= NQKV + NFLS) : false) { }

        if (w < NQKV || w >= NQKV + NFLS) {
            // ================= GEMM tile (QKV or out-proj) =================
            const int isQ = (w < NQKV);
            int rowBase, colBase, K, N;
            const __half *A, *W;
            const float* bias;
            if (isQ) {
                int n = (int)(w >> 6), m = (int)(w & 63);
                rowBase = m * 128; colBase = n * 128;
                K = E_DIM; N = QKV_N;
                A = xh; W = wqkvh; bias = bqkv;
            } else {
                int r = (int)(w - NQKV - NFLS);
                int mm = r >> 3, n = r & 7;
                rowBase = mm * 128; colBase = n * 128;
                K = E_DIM; N = E_DIM;
                A = attn; W = wouth; bias = bout;
                // dep: attn q-block complete
                if (tid == 0) {
                    const unsigned* f = &g_flags[24 + (mm >> 3)];
                    while (ld_acq(f) < 128u) __nanosleep(64);
                }
                __syncthreads();
            }

            const int r0 = tid >> 3;
            const int c8 = (tid & 7) * 8;
            const __half* Aptr = A + (size_t)(rowBase + r0) * K + c8;
            const __half* Wptr = W + (size_t)(colBase + r0) * K + c8;

            float c[4][4][4];
#pragma unroll
            for (int mi = 0; mi < 4; mi++)
#pragma unroll
                for (int nj = 0; nj < 4; nj++)
#pragma unroll
                    for (int r = 0; r < 4; r++) c[mi][nj][r] = 0.f;

            const int wm = (wid >> 2) * 64;
            const int wn = (wid & 3) * 32;

#define GEMM_STAGE(buf, k0)                                                    \
    {                                                                          \
        uint32_t sb_ = sbase + (uint32_t)((buf) * STAGE_BYTES);                \
        _Pragma("unroll")                                                      \
        for (int p = 0; p < 4; p++) {                                          \
            uint32_t so_ = (uint32_t)((r0 + p * 32) * GROWB + (tid & 7) * 16); \
            cp16(sb_ + so_,                       Aptr + (size_t)(p * 32) * K + (k0)); \
            cp16(sb_ + (uint32_t)(128 * GROWB) + so_, Wptr + (size_t)(p * 32) * K + (k0)); \
        }                                                                      \
        cp_commit();                                                           \
    }

            const int T = K >> 6;   // 16
            GEMM_STAGE(0, 0);
            GEMM_STAGE(1, 64);

            int cbuf = 0;
            for (int t = 0; t < T; t++) {
                if (t == T - 1) cp_wait0(); else cp_wait1();
                __syncthreads();
                if (t + 2 < T) {
                    int nb = cbuf + 2; if (nb >= 3) nb -= 3;
                    GEMM_STAGE(nb, (t + 2) << 6);
                }
                const uint32_t Ab = sbase + (uint32_t)(cbuf * STAGE_BYTES);
                const uint32_t Wb = Ab + (uint32_t)(128 * GROWB);
#pragma unroll
                for (int ks = 0; ks < 4; ks++) {
                    const int kk = ks * 16;
                    uint32_t a[4][4], b[4][2];
#pragma unroll
                    for (int mi = 0; mi < 4; mi++)
                        ldm_x4(a[mi], Ab + (uint32_t)((wm + mi * 16 + arow) * GROWB + (kk + acol) * 2));
#pragma unroll
                    for (int njp = 0; njp < 2; njp++)
                        ldm_x4(&b[njp * 2][0],
                               Wb + (uint32_t)((wn + njp * 16 + brow) * GROWB + (kk + bcol) * 2));
#pragma unroll
                    for (int mi = 0; mi < 4; mi++)
#pragma unroll
                        for (int nj = 0; nj < 4; nj++)
                            mma_f16(c[mi][nj], a[mi], b[nj]);
                }
                cbuf++; if (cbuf == 3) cbuf = 0;
            }
#undef GEMM_STAGE

            // epilogue
            float scale = 1.f;
            if (isQ) scale = (colBase < E_DIM) ? QSCALE : 1.f;
#pragma unroll
            for (int mi = 0; mi < 4; mi++) {
#pragma unroll
                for (int nj = 0; nj < 4; nj++) {
                    int row0 = rowBase + wm + mi * 16 + g;
                    int col  = colBase + wn + nj * 8 + tg * 2;
                    float b0 = bias[col], b1 = bias[col + 1];
                    if (isQ) {
                        __half2 v0 = __floats2half2_rn((c[mi][nj][0] + b0) * scale,
                                                       (c[mi][nj][1] + b1) * scale);
                        __half2 v1 = __floats2half2_rn((c[mi][nj][2] + b0) * scale,
                                                       (c[mi][nj][3] + b1) * scale);
                        *(__half2*)(qkv + (size_t)row0 * N + col)       = v0;
                        *(__half2*)(qkv + (size_t)(row0 + 8) * N + col) = v1;
                    } else {
                        float2 v0 = make_float2(c[mi][nj][0] + b0, c[mi][nj][1] + b1);
                        float2 v1 = make_float2(c[mi][nj][2] + b0, c[mi][nj][3] + b1);
                        *(float2*)(out + (size_t)row0 * N + col)       = v0;
                        *(float2*)(out + (size_t)(row0 + 8) * N + col) = v1;
                    }
                }
            }

            if (isQ) {
                __threadfence();
                __syncthreads();
                if (tid == 0) atomicAdd(&g_flags[(int)(w >> 6)], 1u);
            }
        } else {
            // ======================= FLASH tile ============================
            const int r = (int)(w - NQKV);
            const int h  = r >> 6;
            const int t6 = r & 63;
            const int b  = t6 >> 3;
            const int q0 = (t6 & 7) * 128;

            // dep: qkv cols h/2 (Q), 8+h/2 (K), 16+h/2 (V) complete
            if (tid == 0) {
                const int j = h >> 1;
                while (ld_acq(&g_flags[j])      < 64u) __nanosleep(64);
                while (ld_acq(&g_flags[8 + j])  < 64u) __nanosleep(64);
                while (ld_acq(&g_flags[16 + j]) < 64u) __nanosleep(64);
            }
            __syncthreads();

            __half* smh = (__half*)smg;
            __half* Vb0 = smh + 2 * 64 * GSH;
            __half* Vb1 = Vb0 + 64 * GSH;
            const uint32_t sK0 = sbase;
            const uint32_t sV0 = sbase + (uint32_t)(2 * 64 * GROWB);
            const uint32_t sQ  = sbase + (uint32_t)(4 * 64 * GROWB);
            const uint32_t BUF = (uint32_t)(64 * GROWB);

            const int wrow = wid * 16;
            const size_t rstride = (size_t)B_DIM * ROW3E;
            const int r0 = tid >> 3;
            const int c8 = (tid & 7) * 8;
            const __half* kbase0 = qkv + (size_t)b * ROW3E + E_DIM + h * HD;

#define KV_STAGE(kt, buf)                                                      \
    {                                                                          \
        uint32_t sKb_ = sK0 + (buf) * BUF;                                     \
        uint32_t sVb_ = sV0 + (buf) * BUF;                                     \
        _Pragma("unroll")                                                      \
        for (int p = 0; p < 2; p++) {                                          \
            int rr_ = r0 + p * 32;                                             \
            uint32_t so_ = (uint32_t)(rr_ * GROWB + (tid & 7) * 16);           \
            const __half* kb_ = kbase0 + (size_t)((kt) * 64 + rr_) * rstride + c8; \
            cp16(sKb_ + so_, kb_);                                             \
            cp16(sVb_ + so_, kb_ + E_DIM);                                     \
        }                                                                      \
        cp_commit();                                                           \
    }

            {
                const __half* qbase = qkv + (size_t)(q0 * B_DIM + b) * ROW3E + h * HD;
#pragma unroll
                for (int p = 0; p < 4; p++) {
                    int f4 = tid + p * 256;
                    int rr = f4 >> 3;
                    int cc = (f4 & 7) * 8;
                    cp16(sQ + (uint32_t)(rr * GROWB + (f4 & 7) * 16),
                         qbase + (size_t)rr * rstride + cc);
                }
            }
            KV_STAGE(0, 0);
            cp_wait0();
            __syncthreads();

            uint32_t qa[4][4];
#pragma unroll
            for (int ks = 0; ks < 4; ks++)
                ldm_x4(qa[ks], sQ + (uint32_t)((wrow + arow) * GROWB + (ks * 16 + acol) * 2));
            __syncwarp();

            float o[8][4];
#pragma unroll
            for (int nj = 0; nj < 8; nj++)
#pragma unroll
                for (int rr = 0; rr < 4; rr++) o[nj][rr] = 0.f;
            float m0 = -1e30f, m1 = -1e30f, l0 = 0.f, l1 = 0.f;

            for (int kt = 0; kt < 16; kt++) {
                const int cur = kt & 1;
                if (kt + 1 < 16) KV_STAGE(kt + 1, 1 - cur);

                const uint32_t sKc = sK0 + cur * BUF;
                const uint32_t sVc = sV0 + cur * BUF;

                float s[8][4];
#pragma unroll
                for (int nj = 0; nj < 8; nj++)
#pragma unroll
                    for (int rr = 0; rr < 4; rr++) s[nj][rr] = 0.f;

#pragma unroll
                for (int ks = 0; ks < 4; ks++) {
                    const int kk = ks * 16;
                    uint32_t kb[8][2];
#pragma unroll
                    for (int njp = 0; njp < 4; njp++)
                        ldm_x4(&kb[njp * 2][0],
                               sKc + (uint32_t)((njp * 16 + brow) * GROWB + (kk + bcol) * 2));
#pragma unroll
                    for (int nj = 0; nj < 8; nj++)
                        mma_f16(s[nj], qa[ks], kb[nj]);
                }

                float rmax0 = -1e30f, rmax1 = -1e30f;
#pragma unroll
                for (int nj = 0; nj < 8; nj++) {
                    rmax0 = fmaxf(rmax0, fmaxf(s[nj][0], s[nj][1]));
                    rmax1 = fmaxf(rmax1, fmaxf(s[nj][2], s[nj][3]));
                }
                rmax0 = fmaxf(rmax0, __shfl_xor_sync(0xffffffffu, rmax0, 1));
                rmax0 = fmaxf(rmax0, __shfl_xor_sync(0xffffffffu, rmax0, 2));
                rmax1 = fmaxf(rmax1, __shfl_xor_sync(0xffffffffu, rmax1, 1));
                rmax1 = fmaxf(rmax1, __shfl_xor_sync(0xffffffffu, rmax1, 2));

                float nm0 = fmaxf(m0, rmax0), nm1 = fmaxf(m1, rmax1);
                float al0 = exp2f(m0 - nm0), al1 = exp2f(m1 - nm1);
                float rs0 = 0.f, rs1 = 0.f;
#pragma unroll
                for (int nj = 0; nj < 8; nj++) {
                    s[nj][0] = exp2f(s[nj][0] - nm0);
                    s[nj][1] = exp2f(s[nj][1] - nm0);
                    s[nj][2] = exp2f(s[nj][2] - nm1);
                    s[nj][3] = exp2f(s[nj][3] - nm1);
                    rs0 += s[nj][0] + s[nj][1];
                    rs1 += s[nj][2] + s[nj][3];
                }
                rs0 += __shfl_xor_sync(0xffffffffu, rs0, 1);
                rs0 += __shfl_xor_sync(0xffffffffu, rs0, 2);
                rs1 += __shfl_xor_sync(0xffffffffu, rs1, 1);
                rs1 += __shfl_xor_sync(0xffffffffu, rs1, 2);
                l0 = l0 * al0 + rs0;  m0 = nm0;
                l1 = l1 * al1 + rs1;  m1 = nm1;

#pragma unroll
                for (int nj = 0; nj < 8; nj++) {
                    o[nj][0] *= al0; o[nj][1] *= al0;
                    o[nj][2] *= al1; o[nj][3] *= al1;
                }

#pragma unroll
                for (int ks = 0; ks < 4; ks++) {
                    const int kk = ks * 16;
                    uint32_t pa[4];
                    pa[0] = packh2(s[2 * ks    ][0], s[2 * ks    ][1]);
                    pa[1] = packh2(s[2 * ks    ][2], s[2 * ks    ][3]);
                    pa[2] = packh2(s[2 * ks + 1][0], s[2 * ks + 1][1]);
                    pa[3] = packh2(s[2 * ks + 1][2], s[2 * ks + 1][3]);
                    uint32_t vb[8][2];
#pragma unroll
                    for (int njp = 0; njp < 4; njp++)
                        ldm_x4t(&vb[njp * 2][0],
                                sVc + (uint32_t)((kk + vrow) * GROWB + (njp * 16 + vcol) * 2));
#pragma unroll
                    for (int nj = 0; nj < 8; nj++)
                        mma_f16(o[nj], pa, vb[nj]);
                }

                cp_wait0();
                __syncthreads();
            }
#undef KV_STAGE

            float inv0 = 1.0f / l0, inv1 = 1.0f / l1;
#pragma unroll
            for (int nj = 0; nj < 8; nj++) {
                int col = h * HD + nj * 8 + tg * 2;
                int rr = q0 + wrow + g;
                __half2 v0 = __floats2half2_rn(o[nj][0] * inv0, o[nj][1] * inv0);
                __half2 v1 = __floats2half2_rn(o[nj][2] * inv1, o[nj][3] * inv1);
                *(__half2*)(attn + (size_t)(rr * B_DIM + b) * E_DIM + col)       = v0;
                *(__half2*)(attn + (size_t)((rr + 8) * B_DIM + b) * E_DIM + col) = v1;
            }

            __threadfence();
            __syncthreads();
            if (tid == 0) atomicAdd(&g_flags[24 + (t6 & 7)], 1u);
        }

        __syncthreads();   // smem reuse guard before next work item
    }
}

// ---------------------------------------------------------------------------
// Launch
// ---------------------------------------------------------------------------
extern "C" void kernel_launch(void* const* d_in, const int* in_sizes, int n_in,
                              void* d_out, int out_size)
{
    const float* x    = (const float*)d_in[0];
    const float* wqkv = (const float*)d_in[1];
    const float* bqkv = (const float*)d_in[2];
    const float* wout = (const float*)d_in[3];
    const float* bout = (const float*)d_in[4];
    float* out = (float*)d_out;

    __half *qkv, *attn, *xh, *wqkvh, *wouth;
    cudaGetSymbolAddress((void**)&qkv,   g_qkv);
    cudaGetSymbolAddress((void**)&attn,  g_attn);
    cudaGetSymbolAddress((void**)&xh,    g_xh);
    cudaGetSymbolAddress((void**)&wqkvh, g_wqkvh);
    cudaGetSymbolAddress((void**)&wouth, g_wouth);

    int sms = 148;
    cudaDeviceGetAttribute(&sms, cudaDevAttrMultiProcessorCount, 0);
    const int pgrid = 2 * sms;

    cudaFuncSetAttribute(fused_kernel,
                         cudaFuncAttributeMaxDynamicSharedMemorySize, (int)FUSED_SMEM);

    // 0) fused prepass: convert inputs to fp16, reset flags/counter
    {
        int total = NX4 + NW14 + NW24;
        cvt_all_kernel<<<(total + 255) / 256, 256>>>(
            (const float4*)x, (__half2*)xh,
            (const float4*)wqkv, (__half2*)wqkvh,
            (const float4*)wout, (__half2*)wouth);
    }

    // 1) fused persistent kernel: QKV -> flash -> out-proj with overlap
    fused_kernel<<<pgrid, 256, FUSED_SMEM>>>(xh, wqkvh, bqkv, wouth, bout,
                                             qkv, attn, out);
}

// round 15
// speedup vs baseline: 1.0613x; 1.0030x over previous
#include <cuda_runtime.h>
#include <cuda_fp16.h>
#include <math.h>
#include <stdint.h>

// Problem constants
#define L_DIM 1024
#define B_DIM 8
#define E_DIM 1024
#define H_DIM 16
#define HD    64
#define M_ROWS (L_DIM * B_DIM)      // 8192
#define QKV_N  (3 * E_DIM)          // 3072
#define ROW3E  (3 * E_DIM)

// Scratch (allocation-free rule: __device__ globals), all fp16
__device__ __half g_qkv[(size_t)M_ROWS * QKV_N];   // fp16, Q pre-scaled by 0.125*log2e
__device__ __half g_attn[(size_t)M_ROWS * E_DIM];  // fp16 attention output
__device__ __half g_xh[(size_t)M_ROWS * E_DIM];    // fp16 x
__device__ __half g_wqkvh[(size_t)QKV_N * E_DIM];  // fp16 Wqkv
__device__ __half g_wouth[(size_t)E_DIM * E_DIM];  // fp16 Wout
// flags[0..23]=qkv col counts, [24..31]=attn q-block counts, [32]=work counter
__device__ unsigned g_flags[40];

// Work-queue sizes
#define NQKV  1536
#define NFLS  1024
#define NPROJ 512
#define NTOT  (NQKV + NFLS + NPROJ)   // 3072

__device__ __forceinline__ void mma_f16(float* c, const uint32_t* a, const uint32_t* b) {
    asm volatile(
        "mma.sync.aligned.m16n8k16.row.col.f32.f16.f16.f32 "
        "{%0,%1,%2,%3}, {%4,%5,%6,%7}, {%8,%9}, {%0,%1,%2,%3};\n"
        : "+f"(c[0]), "+f"(c[1]), "+f"(c[2]), "+f"(c[3])
        : "r"(a[0]), "r"(a[1]), "r"(a[2]), "r"(a[3]),
          "r"(b[0]), "r"(b[1]));
}

__device__ __forceinline__ void cp16(uint32_t sdst, const void* gsrc) {
    asm volatile("cp.async.cg.shared.global [%0], [%1], 16;\n"
                 :: "r"(sdst), "l"(gsrc));
}
__device__ __forceinline__ void cp_commit() {
    asm volatile("cp.async.commit_group;\n" ::: "memory");
}
__device__ __forceinline__ void cp_wait0() {
    asm volatile("cp.async.wait_group 0;\n" ::: "memory");
}
__device__ __forceinline__ void cp_wait1() {
    asm volatile("cp.async.wait_group 1;\n" ::: "memory");
}

__device__ __forceinline__ void ldm_x4(uint32_t* r, uint32_t addr) {
    asm volatile("ldmatrix.sync.aligned.m8n8.x4.shared.b16 {%0,%1,%2,%3}, [%4];"
        : "=r"(r[0]), "=r"(r[1]), "=r"(r[2]), "=r"(r[3]) : "r"(addr));
}
__device__ __forceinline__ void ldm_x4t(uint32_t* r, uint32_t addr) {
    asm volatile("ldmatrix.sync.aligned.m8n8.x4.trans.shared.b16 {%0,%1,%2,%3}, [%4];"
        : "=r"(r[0]), "=r"(r[1]), "=r"(r[2]), "=r"(r[3]) : "r"(addr));
}

__device__ __forceinline__ uint32_t packh2(float a, float b) {
    __half2 h = __floats2half2_rn(a, b);
    return *(uint32_t*)&h;
}

__device__ __forceinline__ unsigned ld_acq(const unsigned* p) {
    unsigned v;
    asm volatile("ld.global.acquire.gpu.b32 %0, [%1];" : "=r"(v) : "l"(p));
    return v;
}

// ---------------------------------------------------------------------------
// Fused prepass: convert x, Wqkv, Wout to fp16; block 0 resets flags
// ---------------------------------------------------------------------------
#define NX4  (M_ROWS * E_DIM / 4)          // 2097152
#define NW14 (QKV_N * E_DIM / 4)           // 786432
#define NW24 (E_DIM * E_DIM / 4)           // 262144

__global__ void cvt_all_kernel(const float4* __restrict__ x,   __half2* __restrict__ xh,
                               const float4* __restrict__ wq,  __half2* __restrict__ wqh,
                               const float4* __restrict__ wo,  __half2* __restrict__ woh)
{
    if (blockIdx.x == 0 && threadIdx.x < 40) g_flags[threadIdx.x] = 0u;
    int i = blockIdx.x * blockDim.x + threadIdx.x;
    const float4* src; __half2* dst; int j;
    if (i < NX4)                    { src = x;  dst = xh;  j = i; }
    else if (i < NX4 + NW14)        { src = wq; dst = wqh; j = i - NX4; }
    else if (i < NX4 + NW14 + NW24) { src = wo; dst = woh; j = i - NX4 - NW14; }
    else return;
    float4 v = src[j];
    dst[2 * j]     = __floats2half2_rn(v.x, v.y);
    dst[2 * j + 1] = __floats2half2_rn(v.z, v.w);
}

// ---------------------------------------------------------------------------
// Fused persistent kernel with dependency-aware queue orderings:
//  - QKV columns permuted in triples (j, 8+j, 16+j) so flash deps finish early
//  - flash tiles q-major so attn q-blocks complete progressively for proj
// All tile math bit-identical to the R12 champion kernels.
// ---------------------------------------------------------------------------
#define GSH 72                         // smem row stride in halves
#define GROWB 144                      // row bytes
#define STAGE_BYTES (2 * 128 * GROWB)  // 36864
#define QSCALE (0.125f * 1.44269504088896340736f)
#define FUSED_SMEM ((size_t)3 * STAGE_BYTES)   // 110592 (superset of flash's 55296)

__global__ void __launch_bounds__(256, 2) fused_kernel(
    const __half* __restrict__ xh,    const __half* __restrict__ wqkvh,
    const float*  __restrict__ bqkv,  const __half* __restrict__ wouth,
    const float*  __restrict__ bout,  __half* __restrict__ qkv,
    __half* __restrict__ attn,        float* __restrict__ out)
{
    extern __shared__ char smg[];
    __shared__ unsigned w_s;
    const uint32_t sbase = (uint32_t)__cvta_generic_to_shared(smg);

    const int tid  = threadIdx.x;
    const int lane = tid & 31;
    const int wid  = tid >> 5;
    const int g    = lane >> 2;
    const int tg   = lane & 3;

    // ldmatrix lane address components (shared by both tile types)
    const int arow = (lane & 15);
    const int acol = (lane >> 4) * 8;
    const int brow = ((lane >> 4) << 3) + (lane & 7);
    const int bcol = ((lane >> 3) & 1) * 8;
    const int vrow = (lane & 15);
    const int vcol = (lane >> 4) * 8;

    for (;;) {
        if (tid == 0) w_s = atomicAdd(&g_flags[32], 1u);
        __syncthreads();
        const unsigned w = w_s;
        if (w >= NTOT) return;

        if (w < NQKV || w >= NQKV + NFLS) {
            // ================= GEMM tile (QKV or out-proj) =================
            const int isQ = (w < NQKV);
            int rowBase, colBase, K, N, qcol = 0;
            const __half *A, *W;
            const float* bias;
            if (isQ) {
                // column permutation: group gq -> col (gq%3)*8 + gq/3
                int gq = (int)(w >> 6), m = (int)(w & 63);
                qcol = (gq % 3) * 8 + gq / 3;
                rowBase = m * 128; colBase = qcol * 128;
                K = E_DIM; N = QKV_N;
                A = xh; W = wqkvh; bias = bqkv;
            } else {
                int r = (int)(w - NQKV - NFLS);
                int mm = r >> 3, n = r & 7;        // mm-major: q-block order
                rowBase = mm * 128; colBase = n * 128;
                K = E_DIM; N = E_DIM;
                A = attn; W = wouth; bias = bout;
                // dep: attn q-block complete
                if (tid == 0) {
                    const unsigned* f = &g_flags[24 + (mm >> 3)];
                    while (ld_acq(f) < 128u) __nanosleep(64);
                }
                __syncthreads();
            }

            const int r0 = tid >> 3;
            const int c8 = (tid & 7) * 8;
            const __half* Aptr = A + (size_t)(rowBase + r0) * K + c8;
            const __half* Wptr = W + (size_t)(colBase + r0) * K + c8;

            float c[4][4][4];
#pragma unroll
            for (int mi = 0; mi < 4; mi++)
#pragma unroll
                for (int nj = 0; nj < 4; nj++)
#pragma unroll
                    for (int r = 0; r < 4; r++) c[mi][nj][r] = 0.f;

            const int wm = (wid >> 2) * 64;
            const int wn = (wid & 3) * 32;

#define GEMM_STAGE(buf, k0)                                                    \
    {                                                                          \
        uint32_t sb_ = sbase + (uint32_t)((buf) * STAGE_BYTES);                \
        _Pragma("unroll")                                                      \
        for (int p = 0; p < 4; p++) {                                          \
            uint32_t so_ = (uint32_t)((r0 + p * 32) * GROWB + (tid & 7) * 16); \
            cp16(sb_ + so_,                       Aptr + (size_t)(p * 32) * K + (k0)); \
            cp16(sb_ + (uint32_t)(128 * GROWB) + so_, Wptr + (size_t)(p * 32) * K + (k0)); \
        }                                                                      \
        cp_commit();                                                           \
    }

            const int T = K >> 6;   // 16
            GEMM_STAGE(0, 0);
            GEMM_STAGE(1, 64);

            int cbuf = 0;
            for (int t = 0; t < T; t++) {
                if (t == T - 1) cp_wait0(); else cp_wait1();
                __syncthreads();
                if (t + 2 < T) {
                    int nb = cbuf + 2; if (nb >= 3) nb -= 3;
                    GEMM_STAGE(nb, (t + 2) << 6);
                }
                const uint32_t Ab = sbase + (uint32_t)(cbuf * STAGE_BYTES);
                const uint32_t Wb = Ab + (uint32_t)(128 * GROWB);
#pragma unroll
                for (int ks = 0; ks < 4; ks++) {
                    const int kk = ks * 16;
                    uint32_t a[4][4], b[4][2];
#pragma unroll
                    for (int mi = 0; mi < 4; mi++)
                        ldm_x4(a[mi], Ab + (uint32_t)((wm + mi * 16 + arow) * GROWB + (kk + acol) * 2));
#pragma unroll
                    for (int njp = 0; njp < 2; njp++)
                        ldm_x4(&b[njp * 2][0],
                               Wb + (uint32_t)((wn + njp * 16 + brow) * GROWB + (kk + bcol) * 2));
#pragma unroll
                    for (int mi = 0; mi < 4; mi++)
#pragma unroll
                        for (int nj = 0; nj < 4; nj++)
                            mma_f16(c[mi][nj], a[mi], b[nj]);
                }
                cbuf++; if (cbuf == 3) cbuf = 0;
            }
#undef GEMM_STAGE

            // epilogue
            float scale = 1.f;
            if (isQ) scale = (colBase < E_DIM) ? QSCALE : 1.f;
#pragma unroll
            for (int mi = 0; mi < 4; mi++) {
#pragma unroll
                for (int nj = 0; nj < 4; nj++) {
                    int row0 = rowBase + wm + mi * 16 + g;
                    int col  = colBase + wn + nj * 8 + tg * 2;
                    float b0 = bias[col], b1 = bias[col + 1];
                    if (isQ) {
                        __half2 v0 = __floats2half2_rn((c[mi][nj][0] + b0) * scale,
                                                       (c[mi][nj][1] + b1) * scale);
                        __half2 v1 = __floats2half2_rn((c[mi][nj][2] + b0) * scale,
                                                       (c[mi][nj][3] + b1) * scale);
                        *(__half2*)(qkv + (size_t)row0 * N + col)       = v0;
                        *(__half2*)(qkv + (size_t)(row0 + 8) * N + col) = v1;
                    } else {
                        float2 v0 = make_float2(c[mi][nj][0] + b0, c[mi][nj][1] + b1);
                        float2 v1 = make_float2(c[mi][nj][2] + b0, c[mi][nj][3] + b1);
                        *(float2*)(out + (size_t)row0 * N + col)       = v0;
                        *(float2*)(out + (size_t)(row0 + 8) * N + col) = v1;
                    }
                }
            }

            if (isQ) {
                __threadfence();
                __syncthreads();
                if (tid == 0) atomicAdd(&g_flags[qcol], 1u);
            }
        } else {
            // ======================= FLASH tile ============================
            // q-major ordering: q outer, then (h, b)
            const int r  = (int)(w - NQKV);
            const int q0 = (r >> 7) * 128;      // q-block 0..7
            const int rem = r & 127;
            const int h  = rem >> 3;
            const int b  = rem & 7;

            // dep: qkv cols h/2 (Q), 8+h/2 (K), 16+h/2 (V) complete
            if (tid == 0) {
                const int j = h >> 1;
                while (ld_acq(&g_flags[j])      < 64u) __nanosleep(64);
                while (ld_acq(&g_flags[8 + j])  < 64u) __nanosleep(64);
                while (ld_acq(&g_flags[16 + j]) < 64u) __nanosleep(64);
            }
            __syncthreads();

            const uint32_t sK0 = sbase;
            const uint32_t sV0 = sbase + (uint32_t)(2 * 64 * GROWB);
            const uint32_t sQ  = sbase + (uint32_t)(4 * 64 * GROWB);
            const uint32_t BUF = (uint32_t)(64 * GROWB);

            const int wrow = wid * 16;
            const size_t rstride = (size_t)B_DIM * ROW3E;
            const int r0 = tid >> 3;
            const int c8 = (tid & 7) * 8;
            const __half* kbase0 = qkv + (size_t)b * ROW3E + E_DIM + h * HD;

#define KV_STAGE(kt, buf)                                                      \
    {                                                                          \
        uint32_t sKb_ = sK0 + (buf) * BUF;                                     \
        uint32_t sVb_ = sV0 + (buf) * BUF;                                     \
        _Pragma("unroll")                                                      \
        for (int p = 0; p < 2; p++) {                                          \
            int rr_ = r0 + p * 32;                                             \
            uint32_t so_ = (uint32_t)(rr_ * GROWB + (tid & 7) * 16);           \
            const __half* kb_ = kbase0 + (size_t)((kt) * 64 + rr_) * rstride + c8; \
            cp16(sKb_ + so_, kb_);                                             \
            cp16(sVb_ + so_, kb_ + E_DIM);                                     \
        }                                                                      \
        cp_commit();                                                           \
    }

            {
                const __half* qbase = qkv + (size_t)(q0 * B_DIM + b) * ROW3E + h * HD;
#pragma unroll
                for (int p = 0; p < 4; p++) {
                    int f4 = tid + p * 256;
                    int rr = f4 >> 3;
                    int cc = (f4 & 7) * 8;
                    cp16(sQ + (uint32_t)(rr * GROWB + (f4 & 7) * 16),
                         qbase + (size_t)rr * rstride + cc);
                }
            }
            KV_STAGE(0, 0);
            cp_wait0();
            __syncthreads();

            uint32_t qa[4][4];
#pragma unroll
            for (int ks = 0; ks < 4; ks++)
                ldm_x4(qa[ks], sQ + (uint32_t)((wrow + arow) * GROWB + (ks * 16 + acol) * 2));
            __syncwarp();

            float o[8][4];
#pragma unroll
            for (int nj = 0; nj < 8; nj++)
#pragma unroll
                for (int rr = 0; rr < 4; rr++) o[nj][rr] = 0.f;
            float m0 = -1e30f, m1 = -1e30f, l0 = 0.f, l1 = 0.f;

            for (int kt = 0; kt < 16; kt++) {
                const int cur = kt & 1;
                if (kt + 1 < 16) KV_STAGE(kt + 1, 1 - cur);

                const uint32_t sKc = sK0 + cur * BUF;
                const uint32_t sVc = sV0 + cur * BUF;

                float s[8][4];
#pragma unroll
                for (int nj = 0; nj < 8; nj++)
#pragma unroll
                    for (int rr = 0; rr < 4; rr++) s[nj][rr] = 0.f;

#pragma unroll
                for (int ks = 0; ks < 4; ks++) {
                    const int kk = ks * 16;
                    uint32_t kb[8][2];
#pragma unroll
                    for (int njp = 0; njp < 4; njp++)
                        ldm_x4(&kb[njp * 2][0],
                               sKc + (uint32_t)((njp * 16 + brow) * GROWB + (kk + bcol) * 2));
#pragma unroll
                    for (int nj = 0; nj < 8; nj++)
                        mma_f16(s[nj], qa[ks], kb[nj]);
                }

                float rmax0 = -1e30f, rmax1 = -1e30f;
#pragma unroll
                for (int nj = 0; nj < 8; nj++) {
                    rmax0 = fmaxf(rmax0, fmaxf(s[nj][0], s[nj][1]));
                    rmax1 = fmaxf(rmax1, fmaxf(s[nj][2], s[nj][3]));
                }
                rmax0 = fmaxf(rmax0, __shfl_xor_sync(0xffffffffu, rmax0, 1));
                rmax0 = fmaxf(rmax0, __shfl_xor_sync(0xffffffffu, rmax0, 2));
                rmax1 = fmaxf(rmax1, __shfl_xor_sync(0xffffffffu, rmax1, 1));
                rmax1 = fmaxf(rmax1, __shfl_xor_sync(0xffffffffu, rmax1, 2));

                float nm0 = fmaxf(m0, rmax0), nm1 = fmaxf(m1, rmax1);
                float al0 = exp2f(m0 - nm0), al1 = exp2f(m1 - nm1);
                float rs0 = 0.f, rs1 = 0.f;
#pragma unroll
                for (int nj = 0; nj < 8; nj++) {
                    s[nj][0] = exp2f(s[nj][0] - nm0);
                    s[nj][1] = exp2f(s[nj][1] - nm0);
                    s[nj][2] = exp2f(s[nj][2] - nm1);
                    s[nj][3] = exp2f(s[nj][3] - nm1);
                    rs0 += s[nj][0] + s[nj][1];
                    rs1 += s[nj][2] + s[nj][3];
                }
                rs0 += __shfl_xor_sync(0xffffffffu, rs0, 1);
                rs0 += __shfl_xor_sync(0xffffffffu, rs0, 2);
                rs1 += __shfl_xor_sync(0xffffffffu, rs1, 1);
                rs1 += __shfl_xor_sync(0xffffffffu, rs1, 2);
                l0 = l0 * al0 + rs0;  m0 = nm0;
                l1 = l1 * al1 + rs1;  m1 = nm1;

#pragma unroll
                for (int nj = 0; nj < 8; nj++) {
                    o[nj][0] *= al0; o[nj][1] *= al0;
                    o[nj][2] *= al1; o[nj][3] *= al1;
                }

#pragma unroll
                for (int ks = 0; ks < 4; ks++) {
                    const int kk = ks * 16;
                    uint32_t pa[4];
                    pa[0] = packh2(s[2 * ks    ][0], s[2 * ks    ][1]);
                    pa[1] = packh2(s[2 * ks    ][2], s[2 * ks    ][3]);
                    pa[2] = packh2(s[2 * ks + 1][0], s[2 * ks + 1][1]);
                    pa[3] = packh2(s[2 * ks + 1][2], s[2 * ks + 1][3]);
                    uint32_t vb[8][2];
#pragma unroll
                    for (int njp = 0; njp < 4; njp++)
                        ldm_x4t(&vb[njp * 2][0],
                                sVc + (uint32_t)((kk + vrow) * GROWB + (njp * 16 + vcol) * 2));
#pragma unroll
                    for (int nj = 0; nj < 8; nj++)
                        mma_f16(o[nj], pa, vb[nj]);
                }

                cp_wait0();
                __syncthreads();
            }
#undef KV_STAGE

            float inv0 = 1.0f / l0, inv1 = 1.0f / l1;
#pragma unroll
            for (int nj = 0; nj < 8; nj++) {
                int col = h * HD + nj * 8 + tg * 2;
                int rr = q0 + wrow + g;
                __half2 v0 = __floats2half2_rn(o[nj][0] * inv0, o[nj][1] * inv0);
                __half2 v1 = __floats2half2_rn(o[nj][2] * inv1, o[nj][3] * inv1);
                *(__half2*)(attn + (size_t)(rr * B_DIM + b) * E_DIM + col)       = v0;
                *(__half2*)(attn + (size_t)((rr + 8) * B_DIM + b) * E_DIM + col) = v1;
            }

            __threadfence();
            __syncthreads();
            if (tid == 0) atomicAdd(&g_flags[24 + (q0 >> 7)], 1u);
        }

        __syncthreads();   // smem reuse guard before next work item
    }
}

// ---------------------------------------------------------------------------
// Launch
// ---------------------------------------------------------------------------
extern "C" void kernel_launch(void* const* d_in, const int* in_sizes, int n_in,
                              void* d_out, int out_size)
{
    const float* x    = (const float*)d_in[0];
    const float* wqkv = (const float*)d_in[1];
    const float* bqkv = (const float*)d_in[2];
    const float* wout = (const float*)d_in[3];
    const float* bout = (const float*)d_in[4];
    float* out = (float*)d_out;

    __half *qkv, *attn, *xh, *wqkvh, *wouth;
    cudaGetSymbolAddress((void**)&qkv,   g_qkv);
    cudaGetSymbolAddress((void**)&attn,  g_attn);
    cudaGetSymbolAddress((void**)&xh,    g_xh);
    cudaGetSymbolAddress((void**)&wqkvh, g_wqkvh);
    cudaGetSymbolAddress((void**)&wouth, g_wouth);

    int sms = 148;
    cudaDeviceGetAttribute(&sms, cudaDevAttrMultiProcessorCount, 0);
    const int pgrid = 2 * sms;

    cudaFuncSetAttribute(fused_kernel,
                         cudaFuncAttributeMaxDynamicSharedMemorySize, (int)FUSED_SMEM);

    // 0) fused prepass: convert inputs to fp16, reset flags/counter
    {
        int total = NX4 + NW14 + NW24;
        cvt_all_kernel<<<(total + 255) / 256, 256>>>(
            (const float4*)x, (__half2*)xh,
            (const float4*)wqkv, (__half2*)wqkvh,
            (const float4*)wout, (__half2*)wouth);
    }

    // 1) fused persistent kernel: QKV -> flash -> out-proj with overlap
    fused_kernel<<<pgrid, 256, FUSED_SMEM>>>(xh, wqkvh, bqkv, wouth, bout,
                                             qkv, attn, out);
}